// round 1
// baseline (speedup 1.0000x reference)
#include <cuda_runtime.h>
#include <cuda_bf16.h>

#define JN   24
#define DN   256
#define HN   4
#define DHC  64
#define TPB  256
#define EMAX 128

__global__ __launch_bounds__(TPB) void gat_fused_kernel(
    const float* __restrict__ x, const float* __restrict__ W,
    const float* __restrict__ att_src, const float* __restrict__ att_dst,
    const float* __restrict__ bias, const int* __restrict__ edge_index,
    float* __restrict__ out, int E0)
{
    // buf holds x tile during the GEMM, then is overwritten with h
    __shared__ float buf[JN * DN];            // 24 KB
    __shared__ float s_att[2 * DN];           // att_src | att_dst
    __shared__ float s_as[JN * HN], s_ad[JN * HN];
    __shared__ float s_sc[EMAX * HN];
    __shared__ float s_alpha[EMAX * HN];
    __shared__ float s_m[JN * HN], s_den[JN * HN];
    __shared__ int   s_src[EMAX], s_dst[EMAX];

    const int bt  = blockIdx.x;
    const int tid = threadIdx.x;
    const float* xg = x + (size_t)bt * (JN * DN);

    // ---- load x tile (float4, coalesced) ----
    {
        const float4* xg4 = (const float4*)xg;
        float4* b4 = (float4*)buf;
        #pragma unroll
        for (int i = tid; i < JN * DN / 4; i += TPB) b4[i] = xg4[i];
    }
    for (int i = tid; i < DN; i += TPB) {
        s_att[i]      = att_src[i];
        s_att[DN + i] = att_dst[i];
    }
    const int E = E0 + JN;  // add self loops
    for (int i = tid; i < E0; i += TPB) {
        s_src[i] = edge_index[i];
        s_dst[i] = edge_index[E0 + i];
    }
    for (int i = tid; i < JN; i += TPB) { s_src[E0 + i] = i; s_dst[E0 + i] = i; }
    __syncthreads();

    // ---- GEMM: h[j][e] = sum_d x[j][d] * W[d][e] ----
    // thread -> (j-group of 6 rows, 4 consecutive output columns)
    const int jg = tid >> 6;       // 0..3
    const int eq = tid & 63;       // column quad: cols 4*eq .. 4*eq+3
    const int j0 = jg * 6;

    float acc[6][4];
    #pragma unroll
    for (int jj = 0; jj < 6; jj++)
        acc[jj][0] = acc[jj][1] = acc[jj][2] = acc[jj][3] = 0.f;

    const float4* W4 = (const float4*)W;   // each row d = 64 float4
    #pragma unroll 4
    for (int d = 0; d < DN; d++) {
        float4 w = W4[d * 64 + eq];
        #pragma unroll
        for (int jj = 0; jj < 6; jj++) {
            float xv = buf[(j0 + jj) * DN + d];
            acc[jj][0] += xv * w.x;
            acc[jj][1] += xv * w.y;
            acc[jj][2] += xv * w.z;
            acc[jj][3] += xv * w.w;
        }
    }
    __syncthreads();   // everyone done reading x before overwriting buf with h

    #pragma unroll
    for (int jj = 0; jj < 6; jj++) {
        float4* hp = (float4*)&buf[(j0 + jj) * DN + 4 * eq];
        *hp = make_float4(acc[jj][0], acc[jj][1], acc[jj][2], acc[jj][3]);
    }
    __syncthreads();

    // ---- attention dot products: a_s[j][h], a_d[j][h] ----
    if (tid < JN * HN) {
        int j = tid >> 2, hh = tid & 3;
        float as = 0.f, ad = 0.f;
        const float* hrow = &buf[j * DN + hh * DHC];
        #pragma unroll 8
        for (int d = 0; d < DHC; d++) {
            float v = hrow[d];
            as += v * s_att[hh * DHC + d];
            ad += v * s_att[DN + hh * DHC + d];
        }
        s_as[tid] = as;
        s_ad[tid] = ad;
    }
    __syncthreads();

    // ---- per-edge scores with leaky_relu(0.2) ----
    for (int idx = tid; idx < E * HN; idx += TPB) {
        int e = idx >> 2, hh = idx & 3;
        float s = s_as[s_src[e] * HN + hh] + s_ad[s_dst[e] * HN + hh];
        s_sc[idx] = (s >= 0.f) ? s : 0.2f * s;
    }
    __syncthreads();

    // ---- segment max + denom per (dst j, head) ----
    if (tid < JN * HN) {
        int j = tid >> 2, hh = tid & 3;
        float m = -3.402823466e38f;
        for (int e = 0; e < E; e++)
            if (s_dst[e] == j) m = fmaxf(m, s_sc[e * HN + hh]);
        float den = 0.f;
        for (int e = 0; e < E; e++)
            if (s_dst[e] == j) den += __expf(s_sc[e * HN + hh] - m);
        s_m[tid]   = m;
        s_den[tid] = den;
    }
    __syncthreads();

    // ---- alpha per edge ----
    for (int idx = tid; idx < E * HN; idx += TPB) {
        int e = idx >> 2, hh = idx & 3;
        int dj = s_dst[e];
        s_alpha[idx] = __expf(s_sc[idx] - s_m[dj * HN + hh]) / s_den[dj * HN + hh];
    }
    __syncthreads();

    // ---- weighted scatter-add + bias, write out ----
    float* og = out + (size_t)bt * (JN * DN);
    const int hh = eq >> 4;                       // head of columns 4*eq..4*eq+3
    const float4 bv = ((const float4*)bias)[eq];
    #pragma unroll
    for (int jj = 0; jj < 6; jj++) {
        int j = j0 + jj;
        float4 o = bv;
        for (int e = 0; e < E; e++) {
            if (s_dst[e] == j) {
                float a = s_alpha[e * HN + hh];
                const float4 hv = *(const float4*)&buf[s_src[e] * DN + 4 * eq];
                o.x += a * hv.x;
                o.y += a * hv.y;
                o.z += a * hv.z;
                o.w += a * hv.w;
            }
        }
        *(float4*)&og[j * DN + 4 * eq] = o;
    }
}

extern "C" void kernel_launch(void* const* d_in, const int* in_sizes, int n_in,
                              void* d_out, int out_size) {
    const float* x        = (const float*)d_in[0];
    const float* W        = (const float*)d_in[1];
    const float* att_src  = (const float*)d_in[2];
    const float* att_dst  = (const float*)d_in[3];
    const float* bias     = (const float*)d_in[4];
    const int*   edge_idx = (const int*)d_in[5];
    float* out = (float*)d_out;

    const int E0   = in_sizes[5] / 2;          // 46
    const int grid = in_sizes[0] / (JN * DN);  // B*T = 4096

    gat_fused_kernel<<<grid, TPB>>>(x, W, att_src, att_dst, bias, edge_idx, out, E0);
}